// round 8
// baseline (speedup 1.0000x reference)
#include <cuda_runtime.h>
#include <cstdint>

#define D_MODEL 512
#define H_HEADS 8
#define HDIM 64
#define B_BATCH 4
#define N_SEQ 8192
#define NI_SEQ 4096
#define NQ_ROWS (B_BATCH * N_SEQ)   // 32768
#define NK_ROWS (B_BATCH * NI_SEQ)  // 16384

// ---------------- scratch (device globals; no allocations allowed) ----------
__device__ float g_Q[NQ_ROWS * D_MODEL];                       // 64 MB
__device__ float g_K[NK_ROWS * D_MODEL];                       // 32 MB (reused per input)
__device__ float g_V[NK_ROWS * D_MODEL];                       // 32 MB (reused per input)
__device__ float g_ksum[3 * B_BATCH * D_MODEL];                // [i][b][512]
__device__ float g_KV[3 * B_BATCH * H_HEADS * HDIM * HDIM];    // [i][b][h][64][64]

// ---------------- zero small accumulators ----------------------------------
__global__ void zero_small_kernel() {
    int idx = blockIdx.x * 256 + threadIdx.x;
    if (idx < 3 * B_BATCH * H_HEADS * HDIM * HDIM) g_KV[idx] = 0.f;
    if (idx < 3 * B_BATCH * D_MODEL) g_ksum[idx] = 0.f;
}

// ---------------- helpers ---------------------------------------------------
__device__ __forceinline__ float to_tf32(float x) {
    float r;
    asm("cvt.rna.tf32.f32 %0, %1;" : "=f"(r) : "f"(x));
    return r;
}

__device__ __forceinline__ void mma_tf32(float* d, const uint32_t* a, const uint32_t* b) {
    asm volatile(
        "mma.sync.aligned.m16n8k8.row.col.f32.tf32.tf32.f32 "
        "{%0,%1,%2,%3}, {%4,%5,%6,%7}, {%8,%9}, {%0,%1,%2,%3};\n"
        : "+f"(d[0]), "+f"(d[1]), "+f"(d[2]), "+f"(d[3])
        : "r"(a[0]), "r"(a[1]), "r"(a[2]), "r"(a[3]), "r"(b[0]), "r"(b[1]));
}

__device__ __forceinline__ void cp_async16(uint32_t smem_addr, const void* gptr) {
    asm volatile("cp.async.cg.shared.global [%0], [%1], 16;\n"
                 :: "r"(smem_addr), "l"(gptr));
}
__device__ __forceinline__ void cp_commit() {
    asm volatile("cp.async.commit_group;\n" ::: "memory");
}
template <int N>
__device__ __forceinline__ void cp_wait() {
    asm volatile("cp.async.wait_group %0;\n" :: "n"(N) : "memory");
}

// ---------------- TF32 tensor GEMM: C[M,N] = A[M,K] @ B[N,K]^T + bias[N] ----
// Block tile 128(M)x256(N), BK=16, 4-stage cp.async pipeline, 256 threads =
// 8 warps (2m x 4n), warp tile 64x64 (4x8 mma grid). Smem row-major with
// pad 20 -> fragment LDS banks (g*20+c)%32 cover all 32 banks (conflict-free).
#define BKT 16
#define ROWPAD 20
#define STG_AF (128 * ROWPAD)            // 2560 floats
#define STG_BF (256 * ROWPAD)            // 5120 floats
#define STG_FLOATS (STG_AF + STG_BF)     // 7680 floats / stage
#define NSTAGE 4
#define GEMM_SMEM_BYTES (NSTAGE * STG_FLOATS * 4)   // 122880 B

__global__ __launch_bounds__(256, 1) void tf32gemm_nt_bias(
    const float* __restrict__ A, const float* __restrict__ B,
    const float* __restrict__ bias, float* __restrict__ C,
    int M, int N, int K)
{
    extern __shared__ float smem[];

    const int tid  = threadIdx.x;
    const int lane = tid & 31;
    const int wid  = tid >> 5;
    const int wm   = wid >> 2;     // 0..1 -> m offset 0/64
    const int wn   = wid & 3;      // 0..3 -> n offset 0/64/128/192
    const int g    = lane >> 2;    // 0..7
    const int c    = lane & 3;     // 0..3
    const int m0 = blockIdx.y * 128;
    const int n0 = blockIdx.x * 256;

    // copy: A = 512 16B segs (2/thread), B = 1024 segs (4/thread)
    const int ar0 = tid >> 2,          ak0 = (tid & 3) * 4;
    const int ar1 = (tid + 256) >> 2;  // ak same pattern
    const float* Ag0 = A + (size_t)(m0 + ar0) * K + ak0;
    const float* Ag1 = A + (size_t)(m0 + ar1) * K + ak0;
    const float* Bg[4];
    int br[4];
    #pragma unroll
    for (int j = 0; j < 4; j++) {
        int seg = tid + j * 256;
        br[j] = seg >> 2;
        Bg[j] = B + (size_t)(n0 + br[j]) * K + ak0;
    }

    uint32_t smem_base = (uint32_t)__cvta_generic_to_shared(smem);
    const uint32_t sa0 = smem_base + (ar0 * ROWPAD + ak0) * 4;
    const uint32_t sa1 = smem_base + (ar1 * ROWPAD + ak0) * 4;
    uint32_t sb[4];
    #pragma unroll
    for (int j = 0; j < 4; j++)
        sb[j] = smem_base + (STG_AF + br[j] * ROWPAD + ak0) * 4;

    const int NT = K / BKT;

    // prologue: stages 0..2
    #pragma unroll
    for (int t = 0; t < NSTAGE - 1; t++) {
        uint32_t off = (uint32_t)(t * STG_FLOATS * 4);
        int ko = t * BKT;
        cp_async16(sa0 + off, Ag0 + ko);
        cp_async16(sa1 + off, Ag1 + ko);
        #pragma unroll
        for (int j = 0; j < 4; j++) cp_async16(sb[j] + off, Bg[j] + ko);
        cp_commit();
    }

    float acc[4][8][4];
    #pragma unroll
    for (int mf = 0; mf < 4; mf++)
        #pragma unroll
        for (int nf = 0; nf < 8; nf++)
            #pragma unroll
            for (int e = 0; e < 4; e++) acc[mf][nf][e] = 0.f;

    for (int t = 0; t < NT; t++) {
        cp_wait<NSTAGE - 2>();
        __syncthreads();

        // issue stage t + NSTAGE-1
        if (t + NSTAGE - 1 < NT) {
            uint32_t off = (uint32_t)(((t + NSTAGE - 1) % NSTAGE) * STG_FLOATS * 4);
            int ko = (t + NSTAGE - 1) * BKT;
            cp_async16(sa0 + off, Ag0 + ko);
            cp_async16(sa1 + off, Ag1 + ko);
            #pragma unroll
            for (int j = 0; j < 4; j++) cp_async16(sb[j] + off, Bg[j] + ko);
        }
        cp_commit();   // uniform group count

        const float* Ab = smem + (t % NSTAGE) * STG_FLOATS;
        const float* Bb = Ab + STG_AF;

        #pragma unroll
        for (int kf = 0; kf < 2; kf++) {
            const int kb = kf * 8;
            uint32_t afr[4][4], bfr[8][2];
            #pragma unroll
            for (int mf = 0; mf < 4; mf++) {
                const int mr = (wm * 64 + mf * 16 + g) * ROWPAD;
                afr[mf][0] = __float_as_uint(to_tf32(Ab[mr + kb + c]));
                afr[mf][1] = __float_as_uint(to_tf32(Ab[mr + 8 * ROWPAD + kb + c]));
                afr[mf][2] = __float_as_uint(to_tf32(Ab[mr + kb + c + 4]));
                afr[mf][3] = __float_as_uint(to_tf32(Ab[mr + 8 * ROWPAD + kb + c + 4]));
            }
            #pragma unroll
            for (int nf = 0; nf < 8; nf++) {
                const int nr = (wn * 64 + nf * 8 + g) * ROWPAD;
                bfr[nf][0] = __float_as_uint(to_tf32(Bb[nr + kb + c]));
                bfr[nf][1] = __float_as_uint(to_tf32(Bb[nr + kb + c + 4]));
            }
            #pragma unroll
            for (int mf = 0; mf < 4; mf++)
                #pragma unroll
                for (int nf = 0; nf < 8; nf++)
                    mma_tf32(acc[mf][nf], afr[mf], bfr[nf]);
        }
        __syncthreads();
    }

    // epilogue: bias add + store (float2 per fragment row)
    #pragma unroll
    for (int nf = 0; nf < 8; nf++) {
        const int cb = n0 + wn * 64 + nf * 8 + 2 * c;
        const float bv0 = bias[cb], bv1 = bias[cb + 1];
        #pragma unroll
        for (int mf = 0; mf < 4; mf++) {
            const int r = m0 + wm * 64 + mf * 16 + g;
            float2 v0 = make_float2(acc[mf][nf][0] + bv0, acc[mf][nf][1] + bv1);
            float2 v1 = make_float2(acc[mf][nf][2] + bv0, acc[mf][nf][3] + bv1);
            *(float2*)(C + (size_t)r * N + cb) = v0;
            *(float2*)(C + (size_t)(r + 8) * N + cb) = v1;
        }
    }
}

// ---------------- softmax over each 64-col head chunk; optional row mask ----
// grid = rows, block = 256 (8 warps = 8 head chunks = one full row)
// mask is int32 (harness delivers bool as int32)
__global__ __launch_bounds__(256) void softmax64_kernel(
    float* __restrict__ X, const int* __restrict__ mask)
{
    const int row = blockIdx.x;
    const int h = threadIdx.x >> 5;
    const int lane = threadIdx.x & 31;
    float* p = X + (size_t)row * D_MODEL + h * HDIM;

    if (mask) {
        if (mask[row] == 0) {
            p[lane] = 0.f; p[lane + 32] = 0.f;
            return;
        }
    }
    float v0 = p[lane], v1 = p[lane + 32];
    float m = fmaxf(v0, v1);
    #pragma unroll
    for (int o = 16; o; o >>= 1) m = fmaxf(m, __shfl_xor_sync(0xffffffffu, m, o));
    v0 = expf(v0 - m); v1 = expf(v1 - m);
    float s = v0 + v1;
    #pragma unroll
    for (int o = 16; o; o >>= 1) s += __shfl_xor_sync(0xffffffffu, s, o);
    float inv = 1.f / s;
    p[lane] = v0 * inv; p[lane + 32] = v1 * inv;
}

// ---------------- k_sum: column sum of masked-softmaxed K over s ------------
// grid (b=4, 2 col-strips of 256, 32 row chunks of 128)
__global__ __launch_bounds__(256) void colsum_kernel(int i)
{
    const int b = blockIdx.x;
    const int c = blockIdx.y * 256 + threadIdx.x;
    const int s0 = blockIdx.z * 128;
    const float* p = g_K + ((size_t)b * NI_SEQ + s0) * D_MODEL + c;
    float s = 0.f;
    #pragma unroll 8
    for (int r = 0; r < 128; r++) s += p[(size_t)r * D_MODEL];
    atomicAdd(&g_ksum[(i * B_BATCH + b) * D_MODEL + c], s);
}

// ---------------- kv[i][b][h] = K_h^T @ V_h  (64x64, reduce over ni) --------
// grid (32 = b*h, 8 s-splits of 512), block 256, 4x4 microtile
__global__ __launch_bounds__(256) void kv_kernel(int i)
{
    __shared__ float Ks[32][64];
    __shared__ float Vs[32][64];
    const int bh = blockIdx.x;
    const int b = bh >> 3, h = bh & 7;
    const int s0 = blockIdx.y * 512;
    const int tid = threadIdx.x;
    const int tx = tid & 15, ty = tid >> 4;

    const float* Kbase = g_K + (size_t)b * NI_SEQ * D_MODEL + h * HDIM;
    const float* Vbase = g_V + (size_t)b * NI_SEQ * D_MODEL + h * HDIM;

    float acc[4][4];
    #pragma unroll
    for (int d = 0; d < 4; d++)
        #pragma unroll
        for (int e = 0; e < 4; e++) acc[d][e] = 0.f;

    for (int st = 0; st < 512; st += 32) {
        #pragma unroll
        for (int l = 0; l < 2; l++) {
            int idx = tid + l * 256;          // 0..511 float4 slots
            int r = idx >> 4;
            int c4 = (idx & 15) * 4;
            *(float4*)&Ks[r][c4] = *(const float4*)(Kbase + (size_t)(s0 + st + r) * D_MODEL + c4);
            *(float4*)&Vs[r][c4] = *(const float4*)(Vbase + (size_t)(s0 + st + r) * D_MODEL + c4);
        }
        __syncthreads();
        #pragma unroll 8
        for (int ks = 0; ks < 32; ks++) {
            float a[4], v[4];
            *(float4*)a = *(const float4*)&Ks[ks][ty * 4];
            *(float4*)v = *(const float4*)&Vs[ks][tx * 4];
            #pragma unroll
            for (int d = 0; d < 4; d++)
                #pragma unroll
                for (int e = 0; e < 4; e++)
                    acc[d][e] += a[d] * v[e];
        }
        __syncthreads();
    }
    float* out = g_KV + (size_t)((i * B_BATCH + b) * H_HEADS + h) * (HDIM * HDIM);
    #pragma unroll
    for (int d = 0; d < 4; d++)
        #pragma unroll
        for (int e = 0; e < 4; e++)
            atomicAdd(&out[(ty * 4 + d) * HDIM + tx * 4 + e], acc[d][e]);
}

// ---------------- mix: Q <- (q + sum_i (q @ kv_i) * dinv_i) / 3, in place ---
// dinv_i computed in-kernel from ksum. grid (32 = b*h, 128 row tiles of 64),
// block 256 (16x16, 4x4 microtile)
#define MIX_SMEM_FLOATS (64 * 64 + 3 * 64 * 64 + 64 * 3 + 3 * 64)
__global__ __launch_bounds__(256) void mix_kernel()
{
    extern __shared__ float sm[];
    float* Qs  = sm;                              // [64][64]
    float* kvs = sm + 64 * 64;                    // [3][64][64]
    float* dvs = sm + 64 * 64 + 3 * 64 * 64;      // [64][3]
    float* kss = dvs + 64 * 3;                    // [3][64]

    const int bh = blockIdx.x;
    const int b = bh >> 3, h = bh & 7;
    const int r0 = blockIdx.y * 64;
    const int tid = threadIdx.x;
    const int tx = tid & 15, ty = tid >> 4;

    const size_t qbase = ((size_t)b * N_SEQ + r0) * D_MODEL + h * HDIM;
    #pragma unroll
    for (int l = 0; l < 16; l++) {
        int idx = l * 256 + tid;
        int r = idx >> 6, d = idx & 63;
        Qs[idx] = g_Q[qbase + (size_t)r * D_MODEL + d];
    }
    #pragma unroll
    for (int i = 0; i < 3; i++) {
        const float* src = g_KV + (size_t)((i * B_BATCH + b) * H_HEADS + h) * 4096;
        #pragma unroll
        for (int l = 0; l < 16; l++) {
            int idx = l * 256 + tid;
            kvs[i * 4096 + idx] = src[idx];
        }
    }
    if (tid < 192) {   // [i][d]: i = tid>>6, d = tid&63
        int i = tid >> 6, d = tid & 63;
        kss[tid] = g_ksum[(i * B_BATCH + b) * D_MODEL + h * HDIM + d];
    }
    __syncthreads();

    // compute dinv per row: thread t -> row = t>>2, quarter = t&3 (16 dims each)
    {
        const int r = tid >> 2, qq = tid & 3;
        float p0 = 0.f, p1 = 0.f, p2 = 0.f;
        #pragma unroll
        for (int j = 0; j < 16; j++) {
            int d = qq * 16 + j;
            float qv = Qs[r * 64 + d];
            p0 += qv * kss[d];
            p1 += qv * kss[64 + d];
            p2 += qv * kss[128 + d];
        }
        #pragma unroll
        for (int o = 1; o < 4; o <<= 1) {
            p0 += __shfl_xor_sync(0xffffffffu, p0, o);
            p1 += __shfl_xor_sync(0xffffffffu, p1, o);
            p2 += __shfl_xor_sync(0xffffffffu, p2, o);
        }
        if (qq == 0) {
            dvs[r * 3 + 0] = 1.f / p0;
            dvs[r * 3 + 1] = 1.f / p1;
            dvs[r * 3 + 2] = 1.f / p2;
        }
    }
    __syncthreads();

    float acc[3][4][4];
    #pragma unroll
    for (int i = 0; i < 3; i++)
        #pragma unroll
        for (int jr = 0; jr < 4; jr++)
            #pragma unroll
            for (int je = 0; je < 4; je++) acc[i][jr][je] = 0.f;

    #pragma unroll 4
    for (int d = 0; d < 64; d++) {
        float a[4];
        #pragma unroll
        for (int jr = 0; jr < 4; jr++) a[jr] = Qs[(ty * 4 + jr) * 64 + d];
        #pragma unroll
        for (int i = 0; i < 3; i++) {
            float bv[4];
            *(float4*)bv = *(const float4*)&kvs[i * 4096 + d * 64 + tx * 4];
            #pragma unroll
            for (int jr = 0; jr < 4; jr++) {
                acc[i][jr][0] += a[jr] * bv[0];
                acc[i][jr][1] += a[jr] * bv[1];
                acc[i][jr][2] += a[jr] * bv[2];
                acc[i][jr][3] += a[jr] * bv[3];
            }
        }
    }

    const float third = 1.f / 3.f;
    #pragma unroll
    for (int jr = 0; jr < 4; jr++) {
        int r = ty * 4 + jr;
        #pragma unroll
        for (int je = 0; je < 4; je++) {
            int e = tx * 4 + je;
            float y = Qs[r * 64 + e];
            #pragma unroll
            for (int i = 0; i < 3; i++) y += acc[i][jr][je] * dvs[r * 3 + i];
            g_Q[qbase + (size_t)r * D_MODEL + e] = y * third;
        }
    }
}

// ---------------- launcher --------------------------------------------------
extern "C" void kernel_launch(void* const* d_in, const int* in_sizes, int n_in,
                              void* d_out, int out_size)
{
    const float* x    = (const float*)d_in[0];
    const float* emb[3] = { (const float*)d_in[1], (const float*)d_in[2], (const float*)d_in[3] };
    const float* Wq = (const float*)d_in[4];
    const float* bq = (const float*)d_in[5];
    const float* Wk = (const float*)d_in[6];
    const float* bk = (const float*)d_in[7];
    const float* Wv = (const float*)d_in[8];
    const float* bv = (const float*)d_in[9];
    const float* Wo = (const float*)d_in[10];
    const float* bo = (const float*)d_in[11];
    const int* mask[3] = { (const int*)d_in[12], (const int*)d_in[13],
                           (const int*)d_in[14] };
    float* out = (float*)d_out;

    float *Qb = nullptr, *Kb = nullptr, *Vb = nullptr;
    cudaGetSymbolAddress((void**)&Qb, g_Q);
    cudaGetSymbolAddress((void**)&Kb, g_K);
    cudaGetSymbolAddress((void**)&Vb, g_V);
    cudaFuncSetAttribute(mix_kernel, cudaFuncAttributeMaxDynamicSharedMemorySize,
                         MIX_SMEM_FLOATS * sizeof(float));
    cudaFuncSetAttribute(tf32gemm_nt_bias, cudaFuncAttributeMaxDynamicSharedMemorySize,
                         GEMM_SMEM_BYTES);

    zero_small_kernel<<<1536, 256>>>();

    // Q = softmax64(x @ Wq^T + bq)
    tf32gemm_nt_bias<<<dim3(2, 256), 256, GEMM_SMEM_BYTES>>>(x, Wq, bq, Qb, NQ_ROWS, D_MODEL, D_MODEL);
    softmax64_kernel<<<NQ_ROWS, 256>>>(Qb, nullptr);

    for (int i = 0; i < 3; i++) {
        tf32gemm_nt_bias<<<dim3(2, 128), 256, GEMM_SMEM_BYTES>>>(
            emb[i], Wk + (size_t)i * D_MODEL * D_MODEL,
            bk + i * D_MODEL, Kb, NK_ROWS, D_MODEL, D_MODEL);
        softmax64_kernel<<<NK_ROWS, 256>>>(Kb, mask[i]);
        tf32gemm_nt_bias<<<dim3(2, 128), 256, GEMM_SMEM_BYTES>>>(
            emb[i], Wv + (size_t)i * D_MODEL * D_MODEL,
            bv + i * D_MODEL, Vb, NK_ROWS, D_MODEL, D_MODEL);
        colsum_kernel<<<dim3(4, 2, 32), 256>>>(i);
        kv_kernel<<<dim3(32, 8), 256>>>(i);
    }

    mix_kernel<<<dim3(32, 128), 256, MIX_SMEM_FLOATS * sizeof(float)>>>();

    // out = mixed @ Wo^T + bo
    tf32gemm_nt_bias<<<dim3(2, 256), 256, GEMM_SMEM_BYTES>>>(Qb, Wo, bo, out, NQ_ROWS, D_MODEL, D_MODEL);
}

// round 14
// speedup vs baseline: 1.0232x; 1.0232x over previous
#include <cuda_runtime.h>
#include <cstdint>

#define D_MODEL 512
#define H_HEADS 8
#define HDIM 64
#define B_BATCH 4
#define N_SEQ 8192
#define NI_SEQ 4096
#define NQ_ROWS (B_BATCH * N_SEQ)   // 32768
#define NK_ROWS (B_BATCH * NI_SEQ)  // 16384

// ---------------- scratch (device globals; no allocations allowed) ----------
__device__ float g_Q[NQ_ROWS * D_MODEL];                       // 64 MB
__device__ float g_K[NK_ROWS * D_MODEL];                       // 32 MB
__device__ float g_V[NK_ROWS * D_MODEL];                       // 32 MB
__device__ float g_ksum[3 * B_BATCH * D_MODEL];                // [i][b][512]
__device__ float g_KV[3 * B_BATCH * H_HEADS * HDIM * HDIM];    // [i][b][h][64][64]
__device__ float g_Wcvt[8 * D_MODEL * D_MODEL];                // tf32-rounded weights

// ---------------- zero small accumulators ----------------------------------
__global__ void zero_small_kernel() {
    int idx = blockIdx.x * 256 + threadIdx.x;
    if (idx < 3 * B_BATCH * H_HEADS * HDIM * HDIM) g_KV[idx] = 0.f;
    if (idx < 3 * B_BATCH * D_MODEL) g_ksum[idx] = 0.f;
}

// ---------------- helpers ---------------------------------------------------
__device__ __forceinline__ float to_tf32(float x) {
    float r;
    asm("cvt.rna.tf32.f32 %0, %1;" : "=f"(r) : "f"(x));
    return r;
}

__device__ __forceinline__ void mma_tf32(float* d, const uint32_t* a, const uint32_t* b) {
    asm volatile(
        "mma.sync.aligned.m16n8k8.row.col.f32.tf32.tf32.f32 "
        "{%0,%1,%2,%3}, {%4,%5,%6,%7}, {%8,%9}, {%0,%1,%2,%3};\n"
        : "+f"(d[0]), "+f"(d[1]), "+f"(d[2]), "+f"(d[3])
        : "r"(a[0]), "r"(a[1]), "r"(a[2]), "r"(a[3]), "r"(b[0]), "r"(b[1]));
}

__device__ __forceinline__ void cp_async16(uint32_t smem_addr, const void* gptr) {
    asm volatile("cp.async.cg.shared.global [%0], [%1], 16;\n"
                 :: "r"(smem_addr), "l"(gptr));
}
__device__ __forceinline__ void cp_commit() {
    asm volatile("cp.async.commit_group;\n" ::: "memory");
}
template <int N>
__device__ __forceinline__ void cp_wait() {
    asm volatile("cp.async.wait_group %0;\n" :: "n"(N) : "memory");
}

// ---------------- weight prepass: tf32-round, slots [Wq, Wk0,Wv0, Wk1,Wv1, Wk2,Wv2, Wo]
__global__ __launch_bounds__(256) void wcvt_kernel(
    const float* __restrict__ Wq, const float* __restrict__ Wk,
    const float* __restrict__ Wv, const float* __restrict__ Wo)
{
    int idx = blockIdx.x * 256 + threadIdx.x;   // 0 .. 8*256K-1
    int m = idx >> 18;                          // slot 0..7
    int r = idx & 0x3FFFF;
    const float* src;
    if (m == 0)            src = Wq + r;
    else if (m == 7)       src = Wo + r;
    else if (m & 1)        src = Wk + ((m - 1) >> 1) * (D_MODEL * D_MODEL) + r;  // 1,3,5
    else                   src = Wv + ((m - 2) >> 1) * (D_MODEL * D_MODEL) + r;  // 2,4,6
    g_Wcvt[idx] = to_tf32(*src);
}

// ---------------- TF32 tensor GEMM + fused epilogue -------------------------
// C[M, 512] = A[M,512] @ W[Nrows,512]^T + bias, with:
//   mode 0: plain (O)
//   mode 1: per-64-col-chunk softmax (Q)
//   mode 2: KV combined (W has 1024 rows = [Wk;Wv]); cols<512: masked softmax
//           -> C (g_K) with biasA; cols>=512: plain -> C2 (g_V) with biasB.
// Block tile 128(M)x256(N), BK=16, 4-stage cp.async, 8 warps (2m x 4n),
// warp tile 64x64. Each warp's 64 cols = exactly one head chunk -> softmax is
// 16 regs/lane + 2 shfl_xor within the quad (lanes share g = row).
#define BKT 16
#define ROWPAD 20
#define STG_AF (128 * ROWPAD)
#define STG_BF (256 * ROWPAD)
#define STG_FLOATS (STG_AF + STG_BF)
#define NSTAGE 4
#define GEMM_SMEM_BYTES (NSTAGE * STG_FLOATS * 4)   // 122880 B

__global__ __launch_bounds__(256, 1) void tf32gemm_fused(
    const float* __restrict__ A, const float* __restrict__ W,
    const float* __restrict__ biasA, const float* __restrict__ biasB,
    float* __restrict__ C, float* __restrict__ C2,
    const int* __restrict__ mask, int mode)
{
    extern __shared__ float smem[];

    const int tid  = threadIdx.x;
    const int lane = tid & 31;
    const int wid  = tid >> 5;
    const int wm   = wid >> 2;
    const int wn   = wid & 3;
    const int g    = lane >> 2;
    const int c    = lane & 3;
    const int m0 = blockIdx.y * 128;
    const int n0 = blockIdx.x * 256;

    const int ar0 = tid >> 2,          ak0 = (tid & 3) * 4;
    const int ar1 = (tid + 256) >> 2;
    const float* Ag0 = A + (size_t)(m0 + ar0) * 512 + ak0;
    const float* Ag1 = A + (size_t)(m0 + ar1) * 512 + ak0;
    const float* Bg[4];
    int br[4];
    #pragma unroll
    for (int j = 0; j < 4; j++) {
        int seg = tid + j * 256;
        br[j] = seg >> 2;
        Bg[j] = W + (size_t)(n0 + br[j]) * 512 + ak0;
    }

    uint32_t smem_base = (uint32_t)__cvta_generic_to_shared(smem);
    const uint32_t sa0 = smem_base + (ar0 * ROWPAD + ak0) * 4;
    const uint32_t sa1 = smem_base + (ar1 * ROWPAD + ak0) * 4;
    uint32_t sb[4];
    #pragma unroll
    for (int j = 0; j < 4; j++)
        sb[j] = smem_base + (STG_AF + br[j] * ROWPAD + ak0) * 4;

    const int NT = 512 / BKT;   // 32

    #pragma unroll
    for (int t = 0; t < NSTAGE - 1; t++) {
        uint32_t off = (uint32_t)(t * STG_FLOATS * 4);
        int ko = t * BKT;
        cp_async16(sa0 + off, Ag0 + ko);
        cp_async16(sa1 + off, Ag1 + ko);
        #pragma unroll
        for (int j = 0; j < 4; j++) cp_async16(sb[j] + off, Bg[j] + ko);
        cp_commit();
    }

    float acc[4][8][4];
    #pragma unroll
    for (int mf = 0; mf < 4; mf++)
        #pragma unroll
        for (int nf = 0; nf < 8; nf++)
            #pragma unroll
            for (int e = 0; e < 4; e++) acc[mf][nf][e] = 0.f;

    for (int t = 0; t < NT; t++) {
        cp_wait<NSTAGE - 2>();
        __syncthreads();

        if (t + NSTAGE - 1 < NT) {
            uint32_t off = (uint32_t)(((t + NSTAGE - 1) % NSTAGE) * STG_FLOATS * 4);
            int ko = (t + NSTAGE - 1) * BKT;
            cp_async16(sa0 + off, Ag0 + ko);
            cp_async16(sa1 + off, Ag1 + ko);
            #pragma unroll
            for (int j = 0; j < 4; j++) cp_async16(sb[j] + off, Bg[j] + ko);
        }
        cp_commit();

        const float* Ab = smem + (t % NSTAGE) * STG_FLOATS;
        const float* Bb = Ab + STG_AF;

        #pragma unroll
        for (int kf = 0; kf < 2; kf++) {
            const int kb = kf * 8;
            uint32_t afr[4][4], bfr[8][2];
            #pragma unroll
            for (int mf = 0; mf < 4; mf++) {
                const int mr = (wm * 64 + mf * 16 + g) * ROWPAD;
                afr[mf][0] = __float_as_uint(to_tf32(Ab[mr + kb + c]));
                afr[mf][1] = __float_as_uint(to_tf32(Ab[mr + 8 * ROWPAD + kb + c]));
                afr[mf][2] = __float_as_uint(to_tf32(Ab[mr + kb + c + 4]));
                afr[mf][3] = __float_as_uint(to_tf32(Ab[mr + 8 * ROWPAD + kb + c + 4]));
            }
            #pragma unroll
            for (int nf = 0; nf < 8; nf++) {
                const int nr = (wn * 64 + nf * 8 + g) * ROWPAD;
                bfr[nf][0] = __float_as_uint(to_tf32(Bb[nr + kb + c]));
                bfr[nf][1] = __float_as_uint(to_tf32(Bb[nr + kb + c + 4]));
            }
            #pragma unroll
            for (int mf = 0; mf < 4; mf++)
                #pragma unroll
                for (int nf = 0; nf < 8; nf++)
                    mma_tf32(acc[mf][nf], afr[mf], bfr[nf]);
        }
        __syncthreads();
    }

    // ---------------- fused epilogue ----------------
    const int colchunk = n0 + wn * 64;                 // warp's head-chunk base
    const bool vhalf = (mode == 2) && (colchunk >= 512);
    const bool do_sm = (mode == 1) || ((mode == 2) && (colchunk < 512));
    const float* bs = vhalf ? biasB : biasA;
    float* Cw = vhalf ? C2 : C;
    const int cshift = vhalf ? 512 : 0;

    // bias add (pre-softmax, matching reference)
    #pragma unroll
    for (int nf = 0; nf < 8; nf++) {
        const int cb = colchunk + nf * 8 + 2 * c - cshift;
        const float bv0 = bs[cb], bv1 = bs[cb + 1];
        #pragma unroll
        for (int mf = 0; mf < 4; mf++) {
            acc[mf][nf][0] += bv0; acc[mf][nf][1] += bv1;
            acc[mf][nf][2] += bv0; acc[mf][nf][3] += bv1;
        }
    }

    if (do_sm) {
        #pragma unroll
        for (int mf = 0; mf < 4; mf++) {
            #pragma unroll
            for (int rh = 0; rh < 2; rh++) {
                const int e0 = rh * 2;
                const int grow = m0 + wm * 64 + mf * 16 + g + rh * 8;
                const bool dead = (mode == 2) && (mask[grow] == 0);
                float mx = acc[mf][0][e0];
                #pragma unroll
                for (int nf = 0; nf < 8; nf++) {
                    mx = fmaxf(mx, acc[mf][nf][e0]);
                    mx = fmaxf(mx, acc[mf][nf][e0 + 1]);
                }
                mx = fmaxf(mx, __shfl_xor_sync(0xffffffffu, mx, 1));
                mx = fmaxf(mx, __shfl_xor_sync(0xffffffffu, mx, 2));
                float s = 0.f;
                #pragma unroll
                for (int nf = 0; nf < 8; nf++) {
                    float t0 = expf(acc[mf][nf][e0] - mx);
                    float t1 = expf(acc[mf][nf][e0 + 1] - mx);
                    acc[mf][nf][e0] = t0; acc[mf][nf][e0 + 1] = t1;
                    s += t0 + t1;
                }
                s += __shfl_xor_sync(0xffffffffu, s, 1);
                s += __shfl_xor_sync(0xffffffffu, s, 2);
                const float scale = dead ? 0.f : 1.f / s;   // branchless mask
                #pragma unroll
                for (int nf = 0; nf < 8; nf++) {
                    acc[mf][nf][e0] *= scale;
                    acc[mf][nf][e0 + 1] *= scale;
                }
            }
        }
    }

    #pragma unroll
    for (int nf = 0; nf < 8; nf++) {
        const int cb = colchunk + nf * 8 + 2 * c - cshift;
        #pragma unroll
        for (int mf = 0; mf < 4; mf++) {
            const int r = m0 + wm * 64 + mf * 16 + g;
            *(float2*)(Cw + (size_t)r * 512 + cb) =
                make_float2(acc[mf][nf][0], acc[mf][nf][1]);
            *(float2*)(Cw + (size_t)(r + 8) * 512 + cb) =
                make_float2(acc[mf][nf][2], acc[mf][nf][3]);
        }
    }
}

// ---------------- kv[i][b][h] = K_h^T @ V_h (+ fused ksum) ------------------
// grid (32 = b*h, 8 s-splits of 512), block 256, 4x4 microtile.
// Threads 0..63 also accumulate column sums of K (masked rows already 0).
__global__ __launch_bounds__(256) void kv_kernel(int i)
{
    __shared__ float Ks[32][64];
    __shared__ float Vs[32][64];
    const int bh = blockIdx.x;
    const int b = bh >> 3, h = bh & 7;
    const int s0 = blockIdx.y * 512;
    const int tid = threadIdx.x;
    const int tx = tid & 15, ty = tid >> 4;

    const float* Kbase = g_K + (size_t)b * NI_SEQ * D_MODEL + h * HDIM;
    const float* Vbase = g_V + (size_t)b * NI_SEQ * D_MODEL + h * HDIM;

    float acc[4][4];
    #pragma unroll
    for (int d = 0; d < 4; d++)
        #pragma unroll
        for (int e = 0; e < 4; e++) acc[d][e] = 0.f;
    float ksacc = 0.f;

    for (int st = 0; st < 512; st += 32) {
        #pragma unroll
        for (int l = 0; l < 2; l++) {
            int idx = tid + l * 256;
            int r = idx >> 4;
            int c4 = (idx & 15) * 4;
            *(float4*)&Ks[r][c4] = *(const float4*)(Kbase + (size_t)(s0 + st + r) * D_MODEL + c4);
            *(float4*)&Vs[r][c4] = *(const float4*)(Vbase + (size_t)(s0 + st + r) * D_MODEL + c4);
        }
        __syncthreads();
        if (tid < 64) {
            #pragma unroll
            for (int r = 0; r < 32; r++) ksacc += Ks[r][tid];
        }
        #pragma unroll 8
        for (int ks = 0; ks < 32; ks++) {
            float a[4], v[4];
            *(float4*)a = *(const float4*)&Ks[ks][ty * 4];
            *(float4*)v = *(const float4*)&Vs[ks][tx * 4];
            #pragma unroll
            for (int d = 0; d < 4; d++)
                #pragma unroll
                for (int e = 0; e < 4; e++)
                    acc[d][e] += a[d] * v[e];
        }
        __syncthreads();
    }
    float* out = g_KV + (size_t)((i * B_BATCH + b) * H_HEADS + h) * (HDIM * HDIM);
    #pragma unroll
    for (int d = 0; d < 4; d++)
        #pragma unroll
        for (int e = 0; e < 4; e++)
            atomicAdd(&out[(ty * 4 + d) * HDIM + tx * 4 + e], acc[d][e]);
    if (tid < 64)
        atomicAdd(&g_ksum[(i * B_BATCH + b) * D_MODEL + h * HDIM + tid], ksacc);
}

// ---------------- mix: Q <- (q + sum_i (q @ kv_i) * dinv_i) / 3, in place ---
#define MIX_SMEM_FLOATS (64 * 64 + 3 * 64 * 64 + 64 * 3 + 3 * 64)
__global__ __launch_bounds__(256) void mix_kernel()
{
    extern __shared__ float sm[];
    float* Qs  = sm;                              // [64][64]
    float* kvs = sm + 64 * 64;                    // [3][64][64]
    float* dvs = sm + 64 * 64 + 3 * 64 * 64;      // [64][3]
    float* kss = dvs + 64 * 3;                    // [3][64]

    const int bh = blockIdx.x;
    const int b = bh >> 3, h = bh & 7;
    const int r0 = blockIdx.y * 64;
    const int tid = threadIdx.x;
    const int tx = tid & 15, ty = tid >> 4;

    const size_t qbase = ((size_t)b * N_SEQ + r0) * D_MODEL + h * HDIM;
    #pragma unroll
    for (int l = 0; l < 16; l++) {
        int idx = l * 256 + tid;
        int r = idx >> 6, d = idx & 63;
        Qs[idx] = g_Q[qbase + (size_t)r * D_MODEL + d];
    }
    #pragma unroll
    for (int i = 0; i < 3; i++) {
        const float* src = g_KV + (size_t)((i * B_BATCH + b) * H_HEADS + h) * 4096;
        #pragma unroll
        for (int l = 0; l < 16; l++) {
            int idx = l * 256 + tid;
            kvs[i * 4096 + idx] = src[idx];
        }
    }
    if (tid < 192) {
        int i = tid >> 6, d = tid & 63;
        kss[tid] = g_ksum[(i * B_BATCH + b) * D_MODEL + h * HDIM + d];
    }
    __syncthreads();

    {
        const int r = tid >> 2, qq = tid & 3;
        float p0 = 0.f, p1 = 0.f, p2 = 0.f;
        #pragma unroll
        for (int j = 0; j < 16; j++) {
            int d = qq * 16 + j;
            float qv = Qs[r * 64 + d];
            p0 += qv * kss[d];
            p1 += qv * kss[64 + d];
            p2 += qv * kss[128 + d];
        }
        #pragma unroll
        for (int o = 1; o < 4; o <<= 1) {
            p0 += __shfl_xor_sync(0xffffffffu, p0, o);
            p1 += __shfl_xor_sync(0xffffffffu, p1, o);
            p2 += __shfl_xor_sync(0xffffffffu, p2, o);
        }
        if (qq == 0) {
            dvs[r * 3 + 0] = 1.f / p0;
            dvs[r * 3 + 1] = 1.f / p1;
            dvs[r * 3 + 2] = 1.f / p2;
        }
    }
    __syncthreads();

    float acc[3][4][4];
    #pragma unroll
    for (int i = 0; i < 3; i++)
        #pragma unroll
        for (int jr = 0; jr < 4; jr++)
            #pragma unroll
            for (int je = 0; je < 4; je++) acc[i][jr][je] = 0.f;

    #pragma unroll 4
    for (int d = 0; d < 64; d++) {
        float a[4];
        #pragma unroll
        for (int jr = 0; jr < 4; jr++) a[jr] = Qs[(ty * 4 + jr) * 64 + d];
        #pragma unroll
        for (int i = 0; i < 3; i++) {
            float bv[4];
            *(float4*)bv = *(const float4*)&kvs[i * 4096 + d * 64 + tx * 4];
            #pragma unroll
            for (int jr = 0; jr < 4; jr++) {
                acc[i][jr][0] += a[jr] * bv[0];
                acc[i][jr][1] += a[jr] * bv[1];
                acc[i][jr][2] += a[jr] * bv[2];
                acc[i][jr][3] += a[jr] * bv[3];
            }
        }
    }

    const float third = 1.f / 3.f;
    #pragma unroll
    for (int jr = 0; jr < 4; jr++) {
        int r = ty * 4 + jr;
        #pragma unroll
        for (int je = 0; je < 4; je++) {
            int e = tx * 4 + je;
            float y = Qs[r * 64 + e];
            #pragma unroll
            for (int i = 0; i < 3; i++) y += acc[i][jr][je] * dvs[r * 3 + i];
            g_Q[qbase + (size_t)r * D_MODEL + e] = y * third;
        }
    }
}

// ---------------- launcher --------------------------------------------------
extern "C" void kernel_launch(void* const* d_in, const int* in_sizes, int n_in,
                              void* d_out, int out_size)
{
    const float* x    = (const float*)d_in[0];
    const float* emb[3] = { (const float*)d_in[1], (const float*)d_in[2], (const float*)d_in[3] };
    const float* Wq = (const float*)d_in[4];
    const float* bq = (const float*)d_in[5];
    const float* Wk = (const float*)d_in[6];
    const float* bk = (const float*)d_in[7];
    const float* Wv = (const float*)d_in[8];
    const float* bv = (const float*)d_in[9];
    const float* Wo = (const float*)d_in[10];
    const float* bo = (const float*)d_in[11];
    const int* mask[3] = { (const int*)d_in[12], (const int*)d_in[13],
                           (const int*)d_in[14] };
    float* out = (float*)d_out;

    float *Qb = nullptr, *Kb = nullptr, *Vb = nullptr, *Wc = nullptr;
    cudaGetSymbolAddress((void**)&Qb, g_Q);
    cudaGetSymbolAddress((void**)&Kb, g_K);
    cudaGetSymbolAddress((void**)&Vb, g_V);
    cudaGetSymbolAddress((void**)&Wc, g_Wcvt);
    cudaFuncSetAttribute(mix_kernel, cudaFuncAttributeMaxDynamicSharedMemorySize,
                         MIX_SMEM_FLOATS * sizeof(float));
    cudaFuncSetAttribute(tf32gemm_fused, cudaFuncAttributeMaxDynamicSharedMemorySize,
                         GEMM_SMEM_BYTES);

    const size_t WMAT = (size_t)D_MODEL * D_MODEL;   // 262144

    zero_small_kernel<<<1536, 256>>>();
    wcvt_kernel<<<8 * (int)WMAT / 256, 256>>>(Wq, Wk, Wv, Wo);

    // Q = softmax64(x @ Wq^T + bq), fused
    tf32gemm_fused<<<dim3(2, 256), 256, GEMM_SMEM_BYTES>>>(
        x, Wc, bq, nullptr, Qb, nullptr, nullptr, 1);

    for (int i = 0; i < 3; i++) {
        // K (masked softmax) + V in one launch: W = [Wk_i; Wv_i]
        tf32gemm_fused<<<dim3(4, 128), 256, GEMM_SMEM_BYTES>>>(
            emb[i], Wc + (size_t)(1 + 2 * i) * WMAT,
            bk + i * D_MODEL, bv + i * D_MODEL,
            Kb, Vb, mask[i], 2);
        kv_kernel<<<dim3(32, 8), 256>>>(i);   // kv + fused ksum
    }

    mix_kernel<<<dim3(32, 128), 256, MIX_SMEM_FLOATS * sizeof(float)>>>();

    // out = mixed @ Wo^T + bo
    tf32gemm_fused<<<dim3(2, 256), 256, GEMM_SMEM_BYTES>>>(
        Qb, Wc + (size_t)7 * WMAT, bo, nullptr, out, nullptr, nullptr, 0);
}

// round 17
// speedup vs baseline: 1.0506x; 1.0268x over previous
#include <cuda_runtime.h>
#include <cstdint>

#define D_MODEL 512
#define H_HEADS 8
#define HDIM 64
#define B_BATCH 4
#define N_SEQ 8192
#define NI_SEQ 4096
#define NQ_ROWS (B_BATCH * N_SEQ)   // 32768
#define NK_ROWS (B_BATCH * NI_SEQ)  // 16384

// ---------------- scratch (device globals; no allocations allowed) ----------
__device__ float g_Q[NQ_ROWS * D_MODEL];                       // 64 MB
__device__ float g_K[NK_ROWS * D_MODEL];                       // 32 MB
__device__ float g_V[NK_ROWS * D_MODEL];                       // 32 MB
__device__ float g_ksum[3 * B_BATCH * D_MODEL];                // [i][b][512]
__device__ float g_KV[3 * B_BATCH * H_HEADS * HDIM * HDIM];    // [i][b][h][64][64]
__device__ float g_Wcvt[8 * D_MODEL * D_MODEL];                // tf32-rounded weights

// ---------------- zero small accumulators ----------------------------------
__global__ void zero_small_kernel() {
    int idx = blockIdx.x * 256 + threadIdx.x;
    if (idx < 3 * B_BATCH * H_HEADS * HDIM * HDIM) g_KV[idx] = 0.f;
    if (idx < 3 * B_BATCH * D_MODEL) g_ksum[idx] = 0.f;
}

// ---------------- helpers ---------------------------------------------------
__device__ __forceinline__ float to_tf32(float x) {
    float r;
    asm("cvt.rna.tf32.f32 %0, %1;" : "=f"(r) : "f"(x));
    return r;
}

__device__ __forceinline__ void mma_tf32(float* d, const uint32_t* a, const uint32_t* b) {
    asm volatile(
        "mma.sync.aligned.m16n8k8.row.col.f32.tf32.tf32.f32 "
        "{%0,%1,%2,%3}, {%4,%5,%6,%7}, {%8,%9}, {%0,%1,%2,%3};\n"
        : "+f"(d[0]), "+f"(d[1]), "+f"(d[2]), "+f"(d[3])
        : "r"(a[0]), "r"(a[1]), "r"(a[2]), "r"(a[3]), "r"(b[0]), "r"(b[1]));
}

__device__ __forceinline__ void cp_async16(uint32_t smem_addr, const void* gptr) {
    asm volatile("cp.async.cg.shared.global [%0], [%1], 16;\n"
                 :: "r"(smem_addr), "l"(gptr));
}
__device__ __forceinline__ void cp_commit() {
    asm volatile("cp.async.commit_group;\n" ::: "memory");
}
template <int N>
__device__ __forceinline__ void cp_wait() {
    asm volatile("cp.async.wait_group %0;\n" :: "n"(N) : "memory");
}

// ---------------- weight prepass: tf32-round, slots [Wq, Wk0,Wv0, Wk1,Wv1, Wk2,Wv2, Wo]
__global__ __launch_bounds__(256) void wcvt_kernel(
    const float* __restrict__ Wq, const float* __restrict__ Wk,
    const float* __restrict__ Wv, const float* __restrict__ Wo)
{
    int idx = blockIdx.x * 256 + threadIdx.x;
    int m = idx >> 18;
    int r = idx & 0x3FFFF;
    const float* src;
    if (m == 0)            src = Wq + r;
    else if (m == 7)       src = Wo + r;
    else if (m & 1)        src = Wk + ((m - 1) >> 1) * (D_MODEL * D_MODEL) + r;
    else                   src = Wv + ((m - 2) >> 1) * (D_MODEL * D_MODEL) + r;
    g_Wcvt[idx] = to_tf32(*src);
}

// ---------------- TF32 tensor GEMM + fused epilogue -------------------------
// Modes: 0 plain (O); 1 per-64-chunk softmax (Q); 2 KV combined.
// Block tile 128x256, BK=16, 4-stage cp.async, 8 warps (2m x 4n), warp tile
// 64x64. Fragment double-buffering across kf/tile; B-side cvt dropped (weights
// pre-rounded; cvt.rna idempotent). ACVT: round A at fragment load.
#define BKT 16
#define ROWPAD 20
#define STG_AF (128 * ROWPAD)
#define STG_BF (256 * ROWPAD)
#define STG_FLOATS (STG_AF + STG_BF)
#define NSTAGE 4
#define GEMM_SMEM_BYTES (NSTAGE * STG_FLOATS * 4)   // 122880 B

template<bool ACVT>
__device__ __forceinline__ void load_frags(
    uint32_t afr[4][4], uint32_t bfr[8][2],
    const float* __restrict__ Ab, const float* __restrict__ Bb,
    int kb, int wm, int wn, int g, int c)
{
    #pragma unroll
    for (int mf = 0; mf < 4; mf++) {
        const int mr = (wm * 64 + mf * 16 + g) * ROWPAD;
        float a0 = Ab[mr + kb + c];
        float a1 = Ab[mr + 8 * ROWPAD + kb + c];
        float a2 = Ab[mr + kb + c + 4];
        float a3 = Ab[mr + 8 * ROWPAD + kb + c + 4];
        if (ACVT) { a0 = to_tf32(a0); a1 = to_tf32(a1); a2 = to_tf32(a2); a3 = to_tf32(a3); }
        afr[mf][0] = __float_as_uint(a0);
        afr[mf][1] = __float_as_uint(a1);
        afr[mf][2] = __float_as_uint(a2);
        afr[mf][3] = __float_as_uint(a3);
    }
    #pragma unroll
    for (int nf = 0; nf < 8; nf++) {
        const int nr = (wn * 64 + nf * 8 + g) * ROWPAD;
        bfr[nf][0] = __float_as_uint(Bb[nr + kb + c]);
        bfr[nf][1] = __float_as_uint(Bb[nr + kb + c + 4]);
    }
}

template<bool ACVT>
__global__ __launch_bounds__(256, 1) void tf32gemm_fused(
    const float* __restrict__ A, const float* __restrict__ W,
    const float* __restrict__ biasA, const float* __restrict__ biasB,
    float* __restrict__ C, float* __restrict__ C2,
    const int* __restrict__ mask, int mode)
{
    extern __shared__ float smem[];

    const int tid  = threadIdx.x;
    const int lane = tid & 31;
    const int wid  = tid >> 5;
    const int wm   = wid >> 2;
    const int wn   = wid & 3;
    const int g    = lane >> 2;
    const int c    = lane & 3;
    const int m0 = blockIdx.y * 128;
    const int n0 = blockIdx.x * 256;

    const int ar0 = tid >> 2,          ak0 = (tid & 3) * 4;
    const int ar1 = (tid + 256) >> 2;
    const float* Ag0 = A + (size_t)(m0 + ar0) * 512 + ak0;
    const float* Ag1 = A + (size_t)(m0 + ar1) * 512 + ak0;
    const float* Bg[4];
    int br[4];
    #pragma unroll
    for (int j = 0; j < 4; j++) {
        int seg = tid + j * 256;
        br[j] = seg >> 2;
        Bg[j] = W + (size_t)(n0 + br[j]) * 512 + ak0;
    }

    uint32_t smem_base = (uint32_t)__cvta_generic_to_shared(smem);
    const uint32_t sa0 = smem_base + (ar0 * ROWPAD + ak0) * 4;
    const uint32_t sa1 = smem_base + (ar1 * ROWPAD + ak0) * 4;
    uint32_t sb[4];
    #pragma unroll
    for (int j = 0; j < 4; j++)
        sb[j] = smem_base + (STG_AF + br[j] * ROWPAD + ak0) * 4;

    const int NT = 512 / BKT;   // 32

    #pragma unroll
    for (int t = 0; t < NSTAGE - 1; t++) {
        uint32_t off = (uint32_t)(t * STG_FLOATS * 4);
        int ko = t * BKT;
        cp_async16(sa0 + off, Ag0 + ko);
        cp_async16(sa1 + off, Ag1 + ko);
        #pragma unroll
        for (int j = 0; j < 4; j++) cp_async16(sb[j] + off, Bg[j] + ko);
        cp_commit();
    }

    float acc[4][8][4];
    #pragma unroll
    for (int mf = 0; mf < 4; mf++)
        #pragma unroll
        for (int nf = 0; nf < 8; nf++)
            #pragma unroll
            for (int e = 0; e < 4; e++) acc[mf][nf][e] = 0.f;

    uint32_t afr[2][4][4], bfr[2][8][2];

    for (int t = 0; t < NT; t++) {
        cp_wait<1>();            // stages t AND t+1 resident
        __syncthreads();

        if (t + NSTAGE - 1 < NT) {
            uint32_t off = (uint32_t)(((t + NSTAGE - 1) % NSTAGE) * STG_FLOATS * 4);
            int ko = (t + NSTAGE - 1) * BKT;
            cp_async16(sa0 + off, Ag0 + ko);
            cp_async16(sa1 + off, Ag1 + ko);
            #pragma unroll
            for (int j = 0; j < 4; j++) cp_async16(sb[j] + off, Bg[j] + ko);
        }
        cp_commit();

        const float* Ab = smem + (t % NSTAGE) * STG_FLOATS;
        const float* Bb = Ab + STG_AF;

        if (t == 0) load_frags<ACVT>(afr[0], bfr[0], Ab, Bb, 0, wm, wn, g, c);

        // kf=0: prefetch (t, kf=1) into bank 1, then MMA bank 0
        load_frags<ACVT>(afr[1], bfr[1], Ab, Bb, 8, wm, wn, g, c);
        #pragma unroll
        for (int mf = 0; mf < 4; mf++)
            #pragma unroll
            for (int nf = 0; nf < 8; nf++)
                mma_tf32(acc[mf][nf], afr[0][mf], bfr[0][nf]);

        // kf=1: prefetch (t+1, kf=0) into bank 0, then MMA bank 1
        if (t + 1 < NT) {
            const float* Ab1 = smem + ((t + 1) % NSTAGE) * STG_FLOATS;
            load_frags<ACVT>(afr[0], bfr[0], Ab1, Ab1 + STG_AF, 0, wm, wn, g, c);
        }
        #pragma unroll
        for (int mf = 0; mf < 4; mf++)
            #pragma unroll
            for (int nf = 0; nf < 8; nf++)
                mma_tf32(acc[mf][nf], afr[1][mf], bfr[1][nf]);

        __syncthreads();
    }

    // ---------------- fused epilogue ----------------
    const int colchunk = n0 + wn * 64;
    const bool vhalf = (mode == 2) && (colchunk >= 512);
    const bool do_sm = (mode == 1) || ((mode == 2) && (colchunk < 512));
    const float* bs = vhalf ? biasB : biasA;
    float* Cw = vhalf ? C2 : C;
    const int cshift = vhalf ? 512 : 0;

    #pragma unroll
    for (int nf = 0; nf < 8; nf++) {
        const int cb = colchunk + nf * 8 + 2 * c - cshift;
        const float bv0 = bs[cb], bv1 = bs[cb + 1];
        #pragma unroll
        for (int mf = 0; mf < 4; mf++) {
            acc[mf][nf][0] += bv0; acc[mf][nf][1] += bv1;
            acc[mf][nf][2] += bv0; acc[mf][nf][3] += bv1;
        }
    }

    if (do_sm) {
        #pragma unroll
        for (int mf = 0; mf < 4; mf++) {
            #pragma unroll
            for (int rh = 0; rh < 2; rh++) {
                const int e0 = rh * 2;
                const int grow = m0 + wm * 64 + mf * 16 + g + rh * 8;
                const bool dead = (mode == 2) && (mask[grow] == 0);
                float mx = acc[mf][0][e0];
                #pragma unroll
                for (int nf = 0; nf < 8; nf++) {
                    mx = fmaxf(mx, acc[mf][nf][e0]);
                    mx = fmaxf(mx, acc[mf][nf][e0 + 1]);
                }
                mx = fmaxf(mx, __shfl_xor_sync(0xffffffffu, mx, 1));
                mx = fmaxf(mx, __shfl_xor_sync(0xffffffffu, mx, 2));
                float s = 0.f;
                #pragma unroll
                for (int nf = 0; nf < 8; nf++) {
                    float t0 = expf(acc[mf][nf][e0] - mx);
                    float t1 = expf(acc[mf][nf][e0 + 1] - mx);
                    acc[mf][nf][e0] = t0; acc[mf][nf][e0 + 1] = t1;
                    s += t0 + t1;
                }
                s += __shfl_xor_sync(0xffffffffu, s, 1);
                s += __shfl_xor_sync(0xffffffffu, s, 2);
                const float scale = dead ? 0.f : 1.f / s;
                #pragma unroll
                for (int nf = 0; nf < 8; nf++) {
                    acc[mf][nf][e0] *= scale;
                    acc[mf][nf][e0 + 1] *= scale;
                }
            }
        }
    }

    #pragma unroll
    for (int nf = 0; nf < 8; nf++) {
        const int cb = colchunk + nf * 8 + 2 * c - cshift;
        #pragma unroll
        for (int mf = 0; mf < 4; mf++) {
            const int r = m0 + wm * 64 + mf * 16 + g;
            *(float2*)(Cw + (size_t)r * 512 + cb) =
                make_float2(acc[mf][nf][0], acc[mf][nf][1]);
            *(float2*)(Cw + (size_t)(r + 8) * 512 + cb) =
                make_float2(acc[mf][nf][2], acc[mf][nf][3]);
        }
    }
}

// ---------------- kv[i][b][h] = K_h^T @ V_h (+ fused ksum) ------------------
__global__ __launch_bounds__(256) void kv_kernel(int i)
{
    __shared__ float Ks[32][64];
    __shared__ float Vs[32][64];
    const int bh = blockIdx.x;
    const int b = bh >> 3, h = bh & 7;
    const int s0 = blockIdx.y * 512;
    const int tid = threadIdx.x;
    const int tx = tid & 15, ty = tid >> 4;

    const float* Kbase = g_K + (size_t)b * NI_SEQ * D_MODEL + h * HDIM;
    const float* Vbase = g_V + (size_t)b * NI_SEQ * D_MODEL + h * HDIM;

    float acc[4][4];
    #pragma unroll
    for (int d = 0; d < 4; d++)
        #pragma unroll
        for (int e = 0; e < 4; e++) acc[d][e] = 0.f;
    float ksacc = 0.f;

    for (int st = 0; st < 512; st += 32) {
        #pragma unroll
        for (int l = 0; l < 2; l++) {
            int idx = tid + l * 256;
            int r = idx >> 4;
            int c4 = (idx & 15) * 4;
            *(float4*)&Ks[r][c4] = *(const float4*)(Kbase + (size_t)(s0 + st + r) * D_MODEL + c4);
            *(float4*)&Vs[r][c4] = *(const float4*)(Vbase + (size_t)(s0 + st + r) * D_MODEL + c4);
        }
        __syncthreads();
        if (tid < 64) {
            #pragma unroll
            for (int r = 0; r < 32; r++) ksacc += Ks[r][tid];
        }
        #pragma unroll 8
        for (int ks = 0; ks < 32; ks++) {
            float a[4], v[4];
            *(float4*)a = *(const float4*)&Ks[ks][ty * 4];
            *(float4*)v = *(const float4*)&Vs[ks][tx * 4];
            #pragma unroll
            for (int d = 0; d < 4; d++)
                #pragma unroll
                for (int e = 0; e < 4; e++)
                    acc[d][e] += a[d] * v[e];
        }
        __syncthreads();
    }
    float* out = g_KV + (size_t)((i * B_BATCH + b) * H_HEADS + h) * (HDIM * HDIM);
    #pragma unroll
    for (int d = 0; d < 4; d++)
        #pragma unroll
        for (int e = 0; e < 4; e++)
            atomicAdd(&out[(ty * 4 + d) * HDIM + tx * 4 + e], acc[d][e]);
    if (tid < 64)
        atomicAdd(&g_ksum[(i * B_BATCH + b) * D_MODEL + h * HDIM + tid], ksacc);
}

// ---------------- mix: Q <- tf32((q + sum_i (q @ kv_i) * dinv_i) / 3) -------
#define MIX_SMEM_FLOATS (64 * 64 + 3 * 64 * 64 + 64 * 3 + 3 * 64)
__global__ __launch_bounds__(256) void mix_kernel()
{
    extern __shared__ float sm[];
    float* Qs  = sm;
    float* kvs = sm + 64 * 64;
    float* dvs = sm + 64 * 64 + 3 * 64 * 64;
    float* kss = dvs + 64 * 3;

    const int bh = blockIdx.x;
    const int b = bh >> 3, h = bh & 7;
    const int r0 = blockIdx.y * 64;
    const int tid = threadIdx.x;
    const int tx = tid & 15, ty = tid >> 4;

    const size_t qbase = ((size_t)b * N_SEQ + r0) * D_MODEL + h * HDIM;
    #pragma unroll
    for (int l = 0; l < 16; l++) {
        int idx = l * 256 + tid;
        int r = idx >> 6, d = idx & 63;
        Qs[idx] = g_Q[qbase + (size_t)r * D_MODEL + d];
    }
    #pragma unroll
    for (int i = 0; i < 3; i++) {
        const float* src = g_KV + (size_t)((i * B_BATCH + b) * H_HEADS + h) * 4096;
        #pragma unroll
        for (int l = 0; l < 16; l++) {
            int idx = l * 256 + tid;
            kvs[i * 4096 + idx] = src[idx];
        }
    }
    if (tid < 192) {
        int i = tid >> 6, d = tid & 63;
        kss[tid] = g_ksum[(i * B_BATCH + b) * D_MODEL + h * HDIM + d];
    }
    __syncthreads();

    {
        const int r = tid >> 2, qq = tid & 3;
        float p0 = 0.f, p1 = 0.f, p2 = 0.f;
        #pragma unroll
        for (int j = 0; j < 16; j++) {
            int d = qq * 16 + j;
            float qv = Qs[r * 64 + d];
            p0 += qv * kss[d];
            p1 += qv * kss[64 + d];
            p2 += qv * kss[128 + d];
        }
        #pragma unroll
        for (int o = 1; o < 4; o <<= 1) {
            p0 += __shfl_xor_sync(0xffffffffu, p0, o);
            p1 += __shfl_xor_sync(0xffffffffu, p1, o);
            p2 += __shfl_xor_sync(0xffffffffu, p2, o);
        }
        if (qq == 0) {
            dvs[r * 3 + 0] = 1.f / p0;
            dvs[r * 3 + 1] = 1.f / p1;
            dvs[r * 3 + 2] = 1.f / p2;
        }
    }
    __syncthreads();

    float acc[3][4][4];
    #pragma unroll
    for (int i = 0; i < 3; i++)
        #pragma unroll
        for (int jr = 0; jr < 4; jr++)
            #pragma unroll
            for (int je = 0; je < 4; je++) acc[i][jr][je] = 0.f;

    #pragma unroll 4
    for (int d = 0; d < 64; d++) {
        float a[4];
        #pragma unroll
        for (int jr = 0; jr < 4; jr++) a[jr] = Qs[(ty * 4 + jr) * 64 + d];
        #pragma unroll
        for (int i = 0; i < 3; i++) {
            float bv[4];
            *(float4*)bv = *(const float4*)&kvs[i * 4096 + d * 64 + tx * 4];
            #pragma unroll
            for (int jr = 0; jr < 4; jr++) {
                acc[i][jr][0] += a[jr] * bv[0];
                acc[i][jr][1] += a[jr] * bv[1];
                acc[i][jr][2] += a[jr] * bv[2];
                acc[i][jr][3] += a[jr] * bv[3];
            }
        }
    }

    const float third = 1.f / 3.f;
    #pragma unroll
    for (int jr = 0; jr < 4; jr++) {
        int r = ty * 4 + jr;
        #pragma unroll
        for (int je = 0; je < 4; je++) {
            int e = tx * 4 + je;
            float y = Qs[r * 64 + e];
            #pragma unroll
            for (int i = 0; i < 3; i++) y += acc[i][jr][je] * dvs[r * 3 + i];
            // store tf32-rounded: O-GEMM then skips its A-side cvt (exact)
            g_Q[qbase + (size_t)r * D_MODEL + e] = to_tf32(y * third);
        }
    }
}

// ---------------- launcher --------------------------------------------------
extern "C" void kernel_launch(void* const* d_in, const int* in_sizes, int n_in,
                              void* d_out, int out_size)
{
    const float* x    = (const float*)d_in[0];
    const float* emb[3] = { (const float*)d_in[1], (const float*)d_in[2], (const float*)d_in[3] };
    const float* Wq = (const float*)d_in[4];
    const float* bq = (const float*)d_in[5];
    const float* Wk = (const float*)d_in[6];
    const float* bk = (const float*)d_in[7];
    const float* Wv = (const float*)d_in[8];
    const float* bv = (const float*)d_in[9];
    const float* Wo = (const float*)d_in[10];
    const float* bo = (const float*)d_in[11];
    const int* mask[3] = { (const int*)d_in[12], (const int*)d_in[13],
                           (const int*)d_in[14] };
    float* out = (float*)d_out;

    float *Qb = nullptr, *Kb = nullptr, *Vb = nullptr, *Wc = nullptr;
    cudaGetSymbolAddress((void**)&Qb, g_Q);
    cudaGetSymbolAddress((void**)&Kb, g_K);
    cudaGetSymbolAddress((void**)&Vb, g_V);
    cudaGetSymbolAddress((void**)&Wc, g_Wcvt);
    cudaFuncSetAttribute(mix_kernel, cudaFuncAttributeMaxDynamicSharedMemorySize,
                         MIX_SMEM_FLOATS * sizeof(float));
    cudaFuncSetAttribute(tf32gemm_fused<true>, cudaFuncAttributeMaxDynamicSharedMemorySize,
                         GEMM_SMEM_BYTES);
    cudaFuncSetAttribute(tf32gemm_fused<false>, cudaFuncAttributeMaxDynamicSharedMemorySize,
                         GEMM_SMEM_BYTES);

    const size_t WMAT = (size_t)D_MODEL * D_MODEL;   // 262144

    zero_small_kernel<<<1536, 256>>>();
    wcvt_kernel<<<8 * (int)WMAT / 256, 256>>>(Wq, Wk, Wv, Wo);

    // Q = softmax64(x @ Wq^T + bq), fused (A = x, needs cvt)
    tf32gemm_fused<true><<<dim3(2, 256), 256, GEMM_SMEM_BYTES>>>(
        x, Wc, bq, nullptr, Qb, nullptr, nullptr, 1);

    for (int i = 0; i < 3; i++) {
        // K (masked softmax) + V in one launch: W = [Wk_i; Wv_i] (A = emb, cvt)
        tf32gemm_fused<true><<<dim3(4, 128), 256, GEMM_SMEM_BYTES>>>(
            emb[i], Wc + (size_t)(1 + 2 * i) * WMAT,
            bk + i * D_MODEL, bv + i * D_MODEL,
            Kb, Vb, mask[i], 2);
        kv_kernel<<<dim3(32, 8), 256>>>(i);
    }

    mix_kernel<<<dim3(32, 128), 256, MIX_SMEM_FLOATS * sizeof(float)>>>();

    // out = mixed @ Wo^T + bo  (A = g_Q pre-rounded by mix -> no cvt)
    tf32gemm_fused<false><<<dim3(2, 256), 256, GEMM_SMEM_BYTES>>>(
        Qb, Wc + (size_t)7 * WMAT, bo, nullptr, out, nullptr, nullptr, 0);
}